// round 16
// baseline (speedup 1.0000x reference)
#include <cuda_runtime.h>
#include <cuda_fp16.h>
#include <math.h>
#include <stdint.h>

// Problem constants
#define S_LEN   2048
#define E_DIM   1024
#define INNER_D 2048
#define NH_N    4
#define DH_N    512
#define M_ROWS  4096   // B*S
#define BH_N    8      // B*NH
#define STAGES  3

// ---------------- scratch (device globals; no allocs allowed) ----------------
__device__ __half g_xpk   [(size_t)M_ROWS * E_DIM];      // packed fp16 x
__device__ float  g_xinner[(size_t)M_ROWS * 4096];
__device__ float  g_xact  [(size_t)M_ROWS * INNER_D];
__device__ __half g_q     [(size_t)BH_N * S_LEN * DH_N]; // packed fp16
__device__ __half g_k     [(size_t)BH_N * S_LEN * DH_N]; // packed fp16
__device__ __half g_v     [(size_t)BH_N * S_LEN * DH_N]; // fp16 (rounded at producer)
__device__ __half g_vT    [(size_t)BH_N * S_LEN * DH_N]; // packed fp16
__device__ __half g_C     [(size_t)BH_N * S_LEN * S_LEN];// packed fp16 (upper tri stays 0)
__device__ float  g_h     [(size_t)BH_N * S_LEN * DH_N]; // plain
__device__ __half g_hstate[(size_t)M_ROWS * INNER_D];    // packed fp16
__device__ __half g_WupT  [(size_t)4096 * 1024];         // packed fp16
__device__ __half g_WdownT[(size_t)1024 * 2048];         // packed fp16
__device__ float  g_ig    [BH_N * S_LEN];
__device__ float  g_fgp   [BH_N * S_LEN];
__device__ float  g_a     [BH_N * S_LEN];
__device__ float  g_amax  [BH_N * S_LEN];
__device__ float  g_enm   [BH_N * S_LEN];
__device__ float  g_rowsum[BH_N * S_LEN];

// ---------------- helpers ----------------
// packed half index within a row for element k (32-k groups, pair-interleaved,
// per-row group rotation): granule g holds pairs (p_g, p_{g+4}) of both 16-k chunks.
__device__ __forceinline__ int ppk(int r, int k) {
    int c = (k >> 4) & 1, kk = k & 15, p = kk >> 1;
    int g = ((p & 3) + ((r >> 1) & 3)) & 3;
    return (k & ~31) + g * 8 + (p >> 2) * 4 + c * 2 + (kk & 1);
}

__device__ __forceinline__ void mma16(float* d, uint32_t a0, uint32_t a1,
                                      uint32_t a2, uint32_t a3,
                                      uint32_t b0, uint32_t b1) {
    asm volatile(
        "mma.sync.aligned.m16n8k16.row.col.f32.f16.f16.f32 "
        "{%0,%1,%2,%3},{%4,%5,%6,%7},{%8,%9},{%0,%1,%2,%3};"
        : "+f"(d[0]), "+f"(d[1]), "+f"(d[2]), "+f"(d[3])
        : "r"(a0), "r"(a1), "r"(a2), "r"(a3), "r"(b0), "r"(b1));
}
__device__ __forceinline__ void cp16(uint32_t dst, const void* src) {
    asm volatile("cp.async.cg.shared.global [%0], [%1], 16;" :: "r"(dst), "l"(src));
}
__device__ __forceinline__ void cp_commit() {
    asm volatile("cp.async.commit_group;" ::: "memory");
}
template<int N>
__device__ __forceinline__ void cp_wait() {
    asm volatile("cp.async.wait_group %0;" :: "n"(N) : "memory");
}

// ---------------- QK GEMM (MODE 1 only of the old gemm_tc) ------------------
// Block tile 128x128x32, 8 warps (2x4 warp grid, warp tile 64x32), 2 blocks/SM.
// causal decay + fused row-sum; blocks n0 > m0+127 skipped;
// strictly-lower tiles use rank-1 exp factorization;
// C fp16 packed via smem-staged coalesced stores; quad-reduced atomics
__global__ __launch_bounds__(256, 2)
void gemm_qk(const __half* __restrict__ A, const __half* __restrict__ Bm,
             __half* __restrict__ Cv, int Kd, int N,
             long long sA, long long sB, long long sC,
             const float* __restrict__ p1, const float* __restrict__ p2,
             float* __restrict__ rsum, float scale)
{
    const int my = gridDim.y - 1 - blockIdx.y;
    const int m0 = my * 128, n0 = blockIdx.x * 128;
    if (n0 > m0 + 127) return;   // never read by PV

    extern __shared__ char smemc[];   // A: [STAGES][128*64B], B: [STAGES][128*64B]
    const int bz = blockIdx.z;
    A  += (size_t)bz * sA;
    Bm += (size_t)bz * sB;
    const int tid = threadIdx.x, lane = tid & 31, warp = tid >> 5;
    const int wm = warp & 1, wn = warp >> 1;
    const int mbase = wm * 64, nbase = wn * 32;
    const int lr = lane >> 2, t4 = lane & 3;
    const int zb = bz * S_LEN;
    const int T = Kd >> 5;

    float acc[4][4][4];
#pragma unroll
    for (int i = 0; i < 4; i++)
#pragma unroll
        for (int j = 0; j < 4; j++)
#pragma unroll
            for (int r = 0; r < 4; r++) acc[i][j][r] = 0.f;

    const int arow = tid >> 1, agr = tid & 1;
    const __half* gA0 = A  + (size_t)(m0 + arow) * Kd + agr * 16;
    const __half* gB0 = Bm + (size_t)(n0 + arow) * Kd + agr * 16;
    const uint32_t sbase = (uint32_t)__cvta_generic_to_shared(smemc);
    const uint32_t dA = sbase + arow * 64 + agr * 32;
    const uint32_t dB = sbase + STAGES * 8192 + arow * 64 + agr * 32;

#pragma unroll
    for (int p = 0; p < 2; p++) {
        cp16(dA + p * 8192,      gA0 + p * 32);
        cp16(dA + p * 8192 + 16, gA0 + p * 32 + 8);
        cp16(dB + p * 8192,      gB0 + p * 32);
        cp16(dB + p * 8192 + 16, gB0 + p * 32 + 8);
        cp_commit();
    }

    for (int t = 0; t < T; t++) {
        if (t + 1 < T) cp_wait<1>(); else cp_wait<0>();
        __syncthreads();
        if (t + 2 < T) {
            const int stg = (t + 2) % STAGES;
            cp16(dA + stg * 8192,      gA0 + (t + 2) * 32);
            cp16(dA + stg * 8192 + 16, gA0 + (t + 2) * 32 + 8);
            cp16(dB + stg * 8192,      gB0 + (t + 2) * 32);
            cp16(dB + stg * 8192 + 16, gB0 + (t + 2) * 32 + 8);
            cp_commit();
        }
        const int stg = t % STAGES;
        const char* baseA = smemc + stg * 8192;
        const char* baseB = smemc + STAGES * 8192 + stg * 8192;
        uint4 af0[4], af1[4], bf[4];
#pragma unroll
        for (int mt = 0; mt < 4; mt++) {
            int r = mbase + mt * 16 + lr;
            int go = 16 * ((t4 + ((r >> 1) & 3)) & 3);
            af0[mt] = *(const uint4*)(baseA + r * 64 + go);
            af1[mt] = *(const uint4*)(baseA + (r + 8) * 64 + go);
        }
#pragma unroll
        for (int nt = 0; nt < 4; nt++) {
            int rb = nbase + nt * 8 + lr;
            int go = 16 * ((t4 + ((rb >> 1) & 3)) & 3);
            bf[nt] = *(const uint4*)(baseB + rb * 64 + go);
        }
#pragma unroll
        for (int mt = 0; mt < 4; mt++)
#pragma unroll
            for (int nt = 0; nt < 4; nt++) {
                mma16(acc[mt][nt], af0[mt].x, af1[mt].x, af0[mt].z, af1[mt].z,
                      bf[nt].x, bf[nt].z);
                mma16(acc[mt][nt], af0[mt].y, af1[mt].y, af0[mt].w, af1[mt].w,
                      bf[nt].y, bf[nt].w);
            }
    }

    __half* Ch = Cv + (size_t)bz * sC;
    __syncthreads();
    __half* stg = (__half*)smemc;    // [128 rows][136 halves]
    float ac0[4], ac1[4];
#pragma unroll
    for (int nt = 0; nt < 4; nt++) {
        int c = n0 + nbase + nt * 8 + t4 * 2;
        ac0[nt] = p1[zb + c];
        ac1[nt] = p1[zb + c + 1];
    }
    const bool strict = (n0 + 128 <= m0);   // fully below diagonal
    float cf0[4], cf1[4], P = -3.4e38f;
    if (strict) {
#pragma unroll
        for (int nt = 0; nt < 4; nt++)
            P = fmaxf(P, fmaxf(ac0[nt], ac1[nt]));
        P = fmaxf(P, __shfl_xor_sync(0xffffffffu, P, 1));
        P = fmaxf(P, __shfl_xor_sync(0xffffffffu, P, 2));
#pragma unroll
        for (int nt = 0; nt < 4; nt++) {
            cf0[nt] = __expf(ac0[nt] - P);
            cf1[nt] = __expf(ac1[nt] - P);
        }
    }
#pragma unroll
    for (int mt = 0; mt < 4; mt++) {
        int r1 = m0 + mbase + mt * 16 + lr;
        int r2 = r1 + 8;
        float am1 = p2[zb + r1], am2 = p2[zb + r2];
        float rowacc1 = 0.f, rowacc2 = 0.f;
        float rf1 = 0.f, rf2 = 0.f;
        if (strict) {
            rf1 = scale * __expf(P - am1);
            rf2 = scale * __expf(P - am2);
        }
#pragma unroll
        for (int nt = 0; nt < 4; nt++) {
            int c = n0 + nbase + nt * 8 + t4 * 2;
            int cl = c - n0;
            float* a4 = acc[mt][nt];
            float o0, o1, o2, o3;
            if (strict) {
                o0 = a4[0] * cf0[nt] * rf1;
                o1 = a4[1] * cf1[nt] * rf1;
                o2 = a4[2] * cf0[nt] * rf2;
                o3 = a4[3] * cf1[nt] * rf2;
            } else {
                o0 = a4[0] * ((c     <= r1) ? scale * __expf(fminf(ac0[nt] - am1, 0.f)) : 0.f);
                o1 = a4[1] * ((c + 1 <= r1) ? scale * __expf(fminf(ac1[nt] - am1, 0.f)) : 0.f);
                o2 = a4[2] * ((c     <= r2) ? scale * __expf(fminf(ac0[nt] - am2, 0.f)) : 0.f);
                o3 = a4[3] * ((c + 1 <= r2) ? scale * __expf(fminf(ac1[nt] - am2, 0.f)) : 0.f);
            }
            rowacc1 += o0 + o1;
            rowacc2 += o2 + o3;
            *(__half2*)(stg + (r1 - m0) * 136 + ppk(r1, cl)) = __floats2half2_rn(o0, o1);
            *(__half2*)(stg + (r2 - m0) * 136 + ppk(r2, cl)) = __floats2half2_rn(o2, o3);
        }
        rowacc1 += __shfl_xor_sync(0xffffffffu, rowacc1, 1);
        rowacc1 += __shfl_xor_sync(0xffffffffu, rowacc1, 2);
        rowacc2 += __shfl_xor_sync(0xffffffffu, rowacc2, 1);
        rowacc2 += __shfl_xor_sync(0xffffffffu, rowacc2, 2);
        if (t4 == 0) {
            atomicAdd(rsum + zb + r1, rowacc1);
            atomicAdd(rsum + zb + r2, rowacc2);
        }
    }
    __syncthreads();
#pragma unroll
    for (int i = 0; i < 8; i++) {
        int idx = i * 256 + tid;
        int row = idx >> 4, col = idx & 15;
        uint4 vsm = *(const uint4*)(stg + row * 136 + col * 8);
        *(uint4*)(Ch + (size_t)(m0 + row) * N + n0 + col * 8) = vsm;
    }
}

// ---------------- wide GEMM: C[M,N] = A[M,K] @ B[N,K]^T (plain, float out) --
// Block tile 128x256x32, 8 warps (2x4 grid, warp tile 64x64), 1 block/SM.
// Half the LDS traffic per FLOP of the 64x32-warp shape.
__global__ __launch_bounds__(256, 1)
void gemm_wide(const __half* __restrict__ A, const __half* __restrict__ Bm,
               float* __restrict__ Cf, int Kd, int N,
               long long sA, long long sB, long long sC)
{
    const int m0 = blockIdx.y * 128, n0 = blockIdx.x * 256;

    extern __shared__ char smemc[];   // A: [STAGES][128*64B], B: [STAGES][256*64B]
    const int bz = blockIdx.z;
    A  += (size_t)bz * sA;
    Bm += (size_t)bz * sB;
    Cf += (size_t)bz * sC;
    const int tid = threadIdx.x, lane = tid & 31, warp = tid >> 5;
    const int wm = warp & 1, wn = warp >> 1;
    const int mbase = wm * 64, nbase = wn * 64;
    const int lr = lane >> 2, t4 = lane & 3;
    const int T = Kd >> 5;

    float acc[4][8][4];
#pragma unroll
    for (int i = 0; i < 4; i++)
#pragma unroll
        for (int j = 0; j < 8; j++)
#pragma unroll
            for (int r = 0; r < 4; r++) acc[i][j][r] = 0.f;

    const int arow = tid >> 1, agr = tid & 1;
    const __half* gA0 = A  + (size_t)(m0 + arow) * Kd + agr * 16;
    const __half* gB0 = Bm + (size_t)(n0 + tid) * Kd;
    const uint32_t sbase = (uint32_t)__cvta_generic_to_shared(smemc);
    const uint32_t dA = sbase + arow * 64 + agr * 32;
    const uint32_t dB = sbase + STAGES * 8192 + tid * 64;

#pragma unroll
    for (int p = 0; p < 2; p++) {
        cp16(dA + p * 8192,      gA0 + p * 32);
        cp16(dA + p * 8192 + 16, gA0 + p * 32 + 8);
#pragma unroll
        for (int j = 0; j < 4; j++)
            cp16(dB + p * 16384 + j * 16, gB0 + p * 32 + j * 8);
        cp_commit();
    }

    for (int t = 0; t < T; t++) {
        if (t + 1 < T) cp_wait<1>(); else cp_wait<0>();
        __syncthreads();
        if (t + 2 < T) {
            const int stg = (t + 2) % STAGES;
            cp16(dA + stg * 8192,      gA0 + (t + 2) * 32);
            cp16(dA + stg * 8192 + 16, gA0 + (t + 2) * 32 + 8);
#pragma unroll
            for (int j = 0; j < 4; j++)
                cp16(dB + stg * 16384 + j * 16, gB0 + (t + 2) * 32 + j * 8);
            cp_commit();
        }
        const int stg = t % STAGES;
        const char* baseA = smemc + stg * 8192;
        const char* baseB = smemc + STAGES * 8192 + stg * 16384;
        uint4 af0[4], af1[4];
#pragma unroll
        for (int mt = 0; mt < 4; mt++) {
            int r = mbase + mt * 16 + lr;
            int go = 16 * ((t4 + ((r >> 1) & 3)) & 3);
            af0[mt] = *(const uint4*)(baseA + r * 64 + go);
            af1[mt] = *(const uint4*)(baseA + (r + 8) * 64 + go);
        }
#pragma unroll
        for (int half = 0; half < 2; half++) {
            uint4 bf[4];
#pragma unroll
            for (int j = 0; j < 4; j++) {
                int rb = nbase + (half * 4 + j) * 8 + lr;
                int go = 16 * ((t4 + ((rb >> 1) & 3)) & 3);
                bf[j] = *(const uint4*)(baseB + rb * 64 + go);
            }
#pragma unroll
            for (int mt = 0; mt < 4; mt++)
#pragma unroll
                for (int j = 0; j < 4; j++) {
                    float* a4 = acc[mt][half * 4 + j];
                    mma16(a4, af0[mt].x, af1[mt].x, af0[mt].z, af1[mt].z,
                          bf[j].x, bf[j].z);
                    mma16(a4, af0[mt].y, af1[mt].y, af0[mt].w, af1[mt].w,
                          bf[j].y, bf[j].w);
                }
        }
    }

#pragma unroll
    for (int mt = 0; mt < 4; mt++) {
        int r1 = m0 + mbase + mt * 16 + lr;
        int r2 = r1 + 8;
#pragma unroll
        for (int nt = 0; nt < 8; nt++) {
            int c = n0 + nbase + nt * 8 + t4 * 2;
            float* a4 = acc[mt][nt];
            *(float2*)(Cf + (size_t)r1 * N + c) = make_float2(a4[0], a4[1]);
            *(float2*)(Cf + (size_t)r2 * N + c) = make_float2(a4[2], a4[3]);
        }
    }
}

// ---------------- PV GEMM: h[M,512] = diag(inorm) C[M,K] @ vT[512,K]^T ------
// Block tile 128x256x32, 8 warps (2x4 grid, warp tile 64x64), K trunc m0+128.
// inorm computed inline from rowsum/enm.
__global__ __launch_bounds__(256, 1)
void gemm_pv(const __half* __restrict__ A, const __half* __restrict__ Bm,
             float* __restrict__ Cf, int Kd, int N,
             long long sA, long long sB, long long sC,
             const float* __restrict__ rsum, const float* __restrict__ enm)
{
    const int my = gridDim.y - 1 - blockIdx.y;
    const int m0 = my * 128, n0 = blockIdx.x * 256;

    extern __shared__ char smemc[];
    const int bz = blockIdx.z;
    A  += (size_t)bz * sA;
    Bm += (size_t)bz * sB;
    Cf += (size_t)bz * sC;
    const int tid = threadIdx.x, lane = tid & 31, warp = tid >> 5;
    const int wm = warp & 1, wn = warp >> 1;
    const int mbase = wm * 64, nbase = wn * 64;
    const int lr = lane >> 2, t4 = lane & 3;
    const int zb = bz * S_LEN;
    const int T = (m0 + 128) >> 5;

    float acc[4][8][4];
#pragma unroll
    for (int i = 0; i < 4; i++)
#pragma unroll
        for (int j = 0; j < 8; j++)
#pragma unroll
            for (int r = 0; r < 4; r++) acc[i][j][r] = 0.f;

    const int arow = tid >> 1, agr = tid & 1;
    const __half* gA0 = A  + (size_t)(m0 + arow) * Kd + agr * 16;
    const __half* gB0 = Bm + (size_t)(n0 + tid) * Kd;
    const uint32_t sbase = (uint32_t)__cvta_generic_to_shared(smemc);
    const uint32_t dA = sbase + arow * 64 + agr * 32;
    const uint32_t dB = sbase + STAGES * 8192 + tid * 64;

#pragma unroll
    for (int p = 0; p < 2; p++) {
        cp16(dA + p * 8192,      gA0 + p * 32);
        cp16(dA + p * 8192 + 16, gA0 + p * 32 + 8);
#pragma unroll
        for (int j = 0; j < 4; j++)
            cp16(dB + p * 16384 + j * 16, gB0 + p * 32 + j * 8);
        cp_commit();
    }

    for (int t = 0; t < T; t++) {
        if (t + 1 < T) cp_wait<1>(); else cp_wait<0>();
        __syncthreads();
        if (t + 2 < T) {
            const int stg = (t + 2) % STAGES;
            cp16(dA + stg * 8192,      gA0 + (t + 2) * 32);
            cp16(dA + stg * 8192 + 16, gA0 + (t + 2) * 32 + 8);
#pragma unroll
            for (int j = 0; j < 4; j++)
                cp16(dB + stg * 16384 + j * 16, gB0 + (t + 2) * 32 + j * 8);
            cp_commit();
        }
        const int stg = t % STAGES;
        const char* baseA = smemc + stg * 8192;
        const char* baseB = smemc + STAGES * 8192 + stg * 16384;
        uint4 af0[4], af1[4];
#pragma unroll
        for (int mt = 0; mt < 4; mt++) {
            int r = mbase + mt * 16 + lr;
            int go = 16 * ((t4 + ((r >> 1) & 3)) & 3);
            af0[mt] = *(const uint4*)(baseA + r * 64 + go);
            af1[mt] = *(const uint4*)(baseA + (r + 8) * 64 + go);
        }
#pragma unroll
        for (int half = 0; half < 2; half++) {
            uint4 bf[4];
#pragma unroll
            for (int j = 0; j < 4; j++) {
                int rb = nbase + (half * 4 + j) * 8 + lr;
                int go = 16 * ((t4 + ((rb >> 1) & 3)) & 3);
                bf[j] = *(const uint4*)(baseB + rb * 64 + go);
            }
#pragma unroll
            for (int mt = 0; mt < 4; mt++)
#pragma unroll
                for (int j = 0; j < 4; j++) {
                    float* a4 = acc[mt][half * 4 + j];
                    mma16(a4, af0[mt].x, af1[mt].x, af0[mt].z, af1[mt].z,
                          bf[j].x, bf[j].z);
                    mma16(a4, af0[mt].y, af1[mt].y, af0[mt].w, af1[mt].w,
                          bf[j].y, bf[j].w);
                }
        }
    }

#pragma unroll
    for (int mt = 0; mt < 4; mt++) {
        int r1 = m0 + mbase + mt * 16 + lr;
        int r2 = r1 + 8;
        float n1 = fmaxf(fabsf(rsum[zb + r1]), enm[zb + r1]);
        float n2 = fmaxf(fabsf(rsum[zb + r2]), enm[zb + r2]);
        float s1 = 1.f / (n1 + 1e-6f);
        float s2 = 1.f / (n2 + 1e-6f);
#pragma unroll
        for (int nt = 0; nt < 8; nt++) {
            int c = n0 + nbase + nt * 8 + t4 * 2;
            float* a4 = acc[mt][nt];
            *(float2*)(Cf + (size_t)r1 * N + c) = make_float2(a4[0] * s1, a4[1] * s1);
            *(float2*)(Cf + (size_t)r2 * N + c) = make_float2(a4[2] * s2, a4[3] * s2);
        }
    }
}

// ---------------- pack x to fp16 packed (one thread per 32-k group) ---------
__global__ void pack_x_k(const float* __restrict__ in, __half* __restrict__ out)
{
    int g = blockIdx.x * 256 + threadIdx.x;
    int r = g >> 5;
    const float* p = in + (size_t)g * 32;
    float buf[32];
#pragma unroll
    for (int i = 0; i < 8; i++) *(float4*)(buf + 4 * i) = *(const float4*)(p + 4 * i);
    __half hb[32];
#pragma unroll
    for (int j = 0; j < 32; j++) hb[ppk(r, j)] = __float2half_rn(buf[j]);
    uint4* o = (uint4*)(out + (size_t)g * 32);
#pragma unroll
    for (int i = 0; i < 4; i++) o[i] = ((uint4*)hb)[i];
}

// ---------------- transpose + fp16 round + pack (float in) ----------------
__global__ void transpose_pk_k(const float* __restrict__ in, __half* __restrict__ out,
                               int R, int Cc, long long sIn, long long sOut)
{
    __shared__ float tile[32][33];
    in  += (size_t)blockIdx.z * sIn;
    out += (size_t)blockIdx.z * sOut;
    int c0 = blockIdx.x * 32, r0 = blockIdx.y * 32;
    int x = threadIdx.x, y = threadIdx.y;
#pragma unroll
    for (int j = 0; j < 32; j += 8)
        tile[y + j][x] = in[(size_t)(r0 + y + j) * Cc + c0 + x];
    __syncthreads();
#pragma unroll
    for (int j = 0; j < 32; j += 8) {
        int orow = c0 + y + j;
        out[(size_t)orow * R + r0 + ppk(orow, x)] = __float2half_rn(tile[x][y + j]);
    }
}

// ---------------- transpose + pack (half in; values already rounded) --------
__global__ void transpose_pk_h(const __half* __restrict__ in, __half* __restrict__ out,
                               int R, int Cc, long long sIn, long long sOut)
{
    __shared__ __half tile[32][34];
    in  += (size_t)blockIdx.z * sIn;
    out += (size_t)blockIdx.z * sOut;
    int c0 = blockIdx.x * 32, r0 = blockIdx.y * 32;
    int x = threadIdx.x, y = threadIdx.y;
#pragma unroll
    for (int j = 0; j < 32; j += 8)
        tile[y + j][x] = in[(size_t)(r0 + y + j) * Cc + c0 + x];
    __syncthreads();
#pragma unroll
    for (int j = 0; j < 32; j += 8) {
        int orow = c0 + y + j;
        out[(size_t)orow * R + r0 + ppk(orow, x)] = tile[x][y + j];
    }
}

// ---------------- causal depthwise conv (K=4) + swish, 4 elems/thread -------
__global__ void conv_swish_k(const float* __restrict__ xinner,
                             const float* __restrict__ cw,
                             const float* __restrict__ cb,
                             float* __restrict__ xact)
{
    int idx = blockIdx.x * 256 + threadIdx.x;
    int c = (idx << 2) & 2047;
    int r = idx >> 9;
    int s = r & 2047;
    const float* base = xinner + (size_t)r * 4096 + c;
    float4 acc = *(const float4*)(cb + c);
#pragma unroll
    for (int i = 0; i < 4; i++) {
        int sp = s - 3 + i;
        if (sp >= 0) {
            float4 xv = *(const float4*)(base + (long long)(i - 3) * 4096);
            float4 w  = *(const float4*)(cw + i * 2048 + c);
            acc.x = fmaf(xv.x, w.x, acc.x);
            acc.y = fmaf(xv.y, w.y, acc.y);
            acc.z = fmaf(xv.z, w.z, acc.z);
            acc.w = fmaf(xv.w, w.w, acc.w);
        }
    }
    float4 o;
    o.x = acc.x / (1.f + __expf(-acc.x));
    o.y = acc.y / (1.f + __expf(-acc.y));
    o.z = acc.z / (1.f + __expf(-acc.z));
    o.w = acc.w / (1.f + __expf(-acc.w));
    *(float4*)(xact + (size_t)idx * 4) = o;
}

// ---------------- headwise q/k/v + gates: 16 rows/block, weights L1-reused --
__global__ __launch_bounds__(256)
void qkv_gates_k(const float* __restrict__ xinner, const float* __restrict__ xact,
    const float* __restrict__ Wq, const float* __restrict__ Wk, const float* __restrict__ Wv,
    const float* __restrict__ Wig, const float* __restrict__ big,
    const float* __restrict__ Wfg, const float* __restrict__ bfg,
    __half* __restrict__ q, __half* __restrict__ k, __half* __restrict__ v,
    float* __restrict__ ig, float* __restrict__ fgp)
{
    const int tid = threadIdx.x;
    __shared__ float red[8][8];
    const int wid = tid >> 5, lane = tid & 31;

    for (int rr = 0; rr < 16; rr++) {
        const int r = blockIdx.x * 16 + rr;
        const int b = r >> 11, s = r & 2047;
        float igp[4] = {0, 0, 0, 0}, fgv[4] = {0, 0, 0, 0};
#pragma unroll
        for (int g = 0; g < 2; g++) {
            int c4 = tid * 8 + g * 4;
            int ph = c4 >> 2;
            float4 xa = *(const float4*)(xact + (size_t)r * 2048 + c4);
            float4 xm = *(const float4*)(xinner + (size_t)r * 4096 + c4);
            float qv[4], kv[4], vv[4];
            int nh = c4 >> 9, dh0 = c4 & 511;
            size_t rowb = ((size_t)(b * 4 + nh) * 2048 + s) * 512;
            const float4* Wq4 = (const float4*)(Wq + ph * 16);
            const float4* Wk4 = (const float4*)(Wk + ph * 16);
            const float4* Wv4 = (const float4*)(Wv + ph * 16);
#pragma unroll
            for (int o = 0; o < 4; o++) {
                float4 wq = Wq4[o], wk = Wk4[o], wv = Wv4[o];
                float qo = 0.f, ko = 0.f, vo = 0.f;
                qo = fmaf(xa.x, wq.x, qo); qo = fmaf(xa.y, wq.y, qo);
                qo = fmaf(xa.z, wq.z, qo); qo = fmaf(xa.w, wq.w, qo);
                ko = fmaf(xa.x, wk.x, ko); ko = fmaf(xa.y, wk.y, ko);
                ko = fmaf(xa.z, wk.z, ko); ko = fmaf(xa.w, wk.w, ko);
                vo = fmaf(xm.x, wv.x, vo); vo = fmaf(xm.y, wv.y, vo);
                vo = fmaf(xm.z, wv.z, vo); vo = fmaf(xm.w, wv.w, vo);
                qv[o] = qo; kv[o] = ko; vv[o] = vo;
                int c = c4 + o;
                float4 wiq = *(const float4*)(Wig + c * 4);
                float4 wik = *(const float4*)(Wig + (2048 + c) * 4);
                float4 wiv = *(const float4*)(Wig + (4096 + c) * 4);
                float4 wfq = *(const float4*)(Wfg + c * 4);
                float4 wfk = *(const float4*)(Wfg + (2048 + c) * 4);
                float4 wfv = *(const float4*)(Wfg + (4096 + c) * 4);
                const float* aiq = (const float*)&wiq;
                const float* aik = (const float*)&wik;
                const float* aiv = (const float*)&wiv;
                const float* afq = (const float*)&wfq;
                const float* afk = (const float*)&wfk;
                const float* afv = (const float*)&wfv;
#pragma unroll
                for (int n2 = 0; n2 < 4; n2++) {
                    igp[n2] = fmaf(qo, aiq[n2], igp[n2]);
                    igp[n2] = fmaf(ko, aik[n2], igp[n2]);
                    igp[n2] = fmaf(vo, aiv[n2], igp[n2]);
                    fgv[n2] = fmaf(qo, afq[n2], fgv[n2]);
                    fgv[n2] = fmaf(ko, afk[n2], fgv[n2]);
                    fgv[n2] = fmaf(vo, afv[n2], fgv[n2]);
                }
            }
            *(__half2*)(q + rowb + ppk(s, dh0))     = __floats2half2_rn(qv[0], qv[1]);
            *(__half2*)(q + rowb + ppk(s, dh0 + 2)) = __floats2half2_rn(qv[2], qv[3]);
            *(__half2*)(k + rowb + ppk(s, dh0))     = __floats2half2_rn(kv[0], kv[1]);
            *(__half2*)(k + rowb + ppk(s, dh0 + 2)) = __floats2half2_rn(kv[2], kv[3]);
            *(__half2*)(v + rowb + dh0)             = __floats2half2_rn(vv[0], vv[1]);
            *(__half2*)(v + rowb + dh0 + 2)         = __floats2half2_rn(vv[2], vv[3]);
        }
#pragma unroll
        for (int off = 16; off; off >>= 1) {
#pragma unroll
            for (int n2 = 0; n2 < 4; n2++) {
                igp[n2] += __shfl_down_sync(0xffffffffu, igp[n2], off);
                fgv[n2] += __shfl_down_sync(0xffffffffu, fgv[n2], off);
            }
        }
        if (lane == 0) {
#pragma unroll
            for (int n2 = 0; n2 < 4; n2++) { red[wid][n2] = igp[n2]; red[wid][4 + n2] = fgv[n2]; }
        }
        __syncthreads();
        if (tid < 8) {
            float acc = 0.f;
            for (int w = 0; w < 8; w++) acc += red[w][tid];
            int n2 = tid & 3;
            if (tid < 4) ig [(size_t)(b * 4 + n2) * 2048 + s] = acc + big[n2];
            else         fgp[(size_t)(b * 4 + n2) * 2048 + s] = acc + bfg[n2];
        }
        __syncthreads();
    }
}

// ---------------- per-head scans ----------------
__global__ void scan_k(const float* __restrict__ ig, const float* __restrict__ fgp,
                       float* __restrict__ ga, float* __restrict__ gamax,
                       float* __restrict__ genm)
{
    const int bh = blockIdx.x, tid = threadIdx.x;
    const int base = bh * 2048;
    const int lane = tid & 31, warp = tid >> 5;
    float lf[8], aL[8], F[8];
    float s = 0.f;
#pragma unroll
    for (int j = 0; j < 8; j++) {
        float xv = fgp[base + tid * 8 + j];
        lf[j] = fminf(xv, 0.f) - log1pf(expf(-fabsf(xv)));
        s += lf[j];
    }
    __shared__ float wred[8];
    float inc = s;
#pragma unroll
    for (int off = 1; off < 32; off <<= 1) {
        float o = __shfl_up_sync(0xffffffffu, inc, off);
        if (lane >= off) inc += o;
    }
    float exc = __shfl_up_sync(0xffffffffu, inc, 1);
    if (lane == 0) exc = 0.f;
    if (lane == 31) wred[warp] = inc;
    __syncthreads();
    float wofs = 0.f;
#pragma unroll
    for (int w = 0; w < 8; w++) if (w < warp) wofs += wred[w];
    float run = wofs + exc;
#pragma unroll
    for (int j = 0; j < 8; j++) { run += lf[j]; F[j] = run; }
    __syncthreads();

    float mloc = -3.4e38f;
#pragma unroll
    for (int j = 0; j < 8; j++) {
        aL[j] = ig[base + tid * 8 + j] - F[j];
        mloc = fmaxf(mloc, aL[j]);
    }
    float minc = mloc;
#pragma unroll
    for (int off = 1; off < 32; off <<= 1) {
        float o = __shfl_up_sync(0xffffffffu, minc, off);
        if (lane >= off) minc = fmaxf(minc, o);
    }
    float mexc = __shfl_up_sync(0xffffffffu, minc, 1);
    if (lane == 0) mexc = -3.4e38f;
    if (lane == 31) wred[warp] = minc;
    __syncthreads();
    float wm = -3.4e38f;
#pragma unroll
    for (int w = 0; w < 8; w++) if (w < warp) wm = fmaxf(wm, wred[w]);
    float rm = fmaxf(wm, mexc);
#pragma unroll
    for (int j = 0; j < 8; j++) {
        rm = fmaxf(rm, aL[j]);
        int idx = base + tid * 8 + j;
        ga[idx] = aL[j];
        gamax[idx] = rm;
        genm[idx] = expf(-(F[j] + rm));
    }
}

// ---------------- layernorm + skip + swish(z): warp-per-(row,head) ----------
__global__ __launch_bounds__(256)
void ln_fuse_k(const float* __restrict__ h, const float* __restrict__ xact,
    const float* __restrict__ xinner, const float* __restrict__ nw,
    const float* __restrict__ sk, __half* __restrict__ hstate)
{
    const int warp = threadIdx.x >> 5, lane = threadIdx.x & 31;
    const int idx = blockIdx.x * 8 + warp;     // [0, 16384)
    const int r = idx >> 2, nh = idx & 3;
    const int b = r >> 11, s = r & 2047;
    const float* hp = h + ((size_t)(b * 4 + nh) * 2048 + s) * 512;

    float4 hv[4];
    float sum = 0.f;
#pragma unroll
    for (int j = 0; j < 4; j++) {
        hv[j] = *(const float4*)(hp + j * 128 + lane * 4);
        sum += hv[j].x + hv[j].y + hv[j].z + hv[j].w;
    }
#pragma unroll
    for (int off = 16; off; off >>= 1) sum += __shfl_xor_sync(0xffffffffu, sum, off);
    const float mu = sum * (1.f / 512.f);

    float sq = 0.f;
#pragma unroll
    for (int j = 0; j < 4; j++) {
        float dx = hv[j].x - mu, dy = hv[j].y - mu, dz = hv[j].z - mu, dw = hv[j].w - mu;
        sq += dx * dx + dy * dy + dz * dz + dw * dw;
    }
#pragma unroll
    for (int off = 16; off; off >>= 1) sq += __shfl_xor_sync(0xffffffffu, sq, off);
    const float rstd = rsqrtf(sq * (1.f / 512.f) + 1e-6f);

    __half* hb = hstate + (size_t)r * 2048;
#pragma unroll
    for (int j = 0; j < 4; j++) {
        int c0 = nh * 512 + j * 128 + lane * 4;
        float4 nwv = *(const float4*)(nw + c0);
        float4 skv = *(const float4*)(sk + c0);
        float4 xav = *(const float4*)(xact + (size_t)r * 2048 + c0);
        float4 zv  = *(const float4*)(xinner + (size_t)r * 4096 + 2048 + c0);
        float o0 = ((hv[j].x - mu) * rstd * nwv.x + skv.x * xav.x) * (zv.x / (1.f + __expf(-zv.x)));
        float o1 = ((hv[j].y - mu) * rstd * nwv.y + skv.y * xav.y) * (zv.y / (1.f + __expf(-zv.y)));
        float o2 = ((hv[j].z - mu) * rstd * nwv.z + skv.z * xav.z) * (zv.z / (1.f + __expf(-zv.z)));
        float o3 = ((hv[j].w - mu) * rstd * nwv.w + skv.w * xav.w) * (zv.w / (1.f + __expf(-zv.w)));
        *(__half2*)(hb + ppk(r, c0))     = __floats2half2_rn(o0, o1);
        *(__half2*)(hb + ppk(r, c0 + 2)) = __floats2half2_rn(o2, o3);
    }
}

// ---------------- launch ----------------
extern "C" void kernel_launch(void* const* d_in, const int* in_sizes, int n_in,
                              void* d_out, int out_size)
{
    (void)in_sizes; (void)n_in; (void)out_size;
    const float* x      = (const float*)d_in[0];
    const float* W_up   = (const float*)d_in[1];
    const float* conv_w = (const float*)d_in[2];
    const float* conv_b = (const float*)d_in[3];
    const float* Wq     = (const float*)d_in[4];
    const float* Wk     = (const float*)d_in[5];
    const float* Wv     = (const float*)d_in[6];
    const float* W_ig   = (const float*)d_in[7];
    const float* b_ig   = (const float*)d_in[8];
    const float* W_fg   = (const float*)d_in[9];
    const float* b_fg   = (const float*)d_in[10];
    const float* norm_w = (const float*)d_in[11];
    const float* skipw  = (const float*)d_in[12];
    const float* W_down = (const float*)d_in[13];
    float* out = (float*)d_out;

    __half *xpk, *q, *k, *v, *vT, *Cb, *hstate, *WupT, *WdownT;
    float *xinner, *xact, *h;
    float *ig, *fgp, *a, *amax, *enm, *rowsum;
    cudaGetSymbolAddress((void**)&xpk,    g_xpk);
    cudaGetSymbolAddress((void**)&xinner, g_xinner);
    cudaGetSymbolAddress((void**)&xact,   g_xact);
    cudaGetSymbolAddress((void**)&q,      g_q);
    cudaGetSymbolAddress((void**)&k,      g_k);
    cudaGetSymbolAddress((void**)&v,      g_v);
    cudaGetSymbolAddress((void**)&vT,     g_vT);
    cudaGetSymbolAddress((void**)&Cb,     g_C);
    cudaGetSymbolAddress((void**)&h,      g_h);
    cudaGetSymbolAddress((void**)&hstate, g_hstate);
    cudaGetSymbolAddress((void**)&WupT,   g_WupT);
    cudaGetSymbolAddress((void**)&WdownT, g_WdownT);
    cudaGetSymbolAddress((void**)&ig,     g_ig);
    cudaGetSymbolAddress((void**)&fgp,    g_fgp);
    cudaGetSymbolAddress((void**)&a,      g_a);
    cudaGetSymbolAddress((void**)&amax,   g_amax);
    cudaGetSymbolAddress((void**)&enm,    g_enm);
    cudaGetSymbolAddress((void**)&rowsum, g_rowsum);

    const int SMEM   = STAGES * (8192 + 8192);    // 48 KB (QK)
    const int SMEMW  = STAGES * (8192 + 16384);   // 72 KB (wide / PV)
    cudaFuncSetAttribute((const void*)gemm_qk,   cudaFuncAttributeMaxDynamicSharedMemorySize, SMEM);
    cudaFuncSetAttribute((const void*)gemm_wide, cudaFuncAttributeMaxDynamicSharedMemorySize, SMEMW);
    cudaFuncSetAttribute((const void*)gemm_pv,   cudaFuncAttributeMaxDynamicSharedMemorySize, SMEMW);

    const long long sQKV = (long long)S_LEN * DH_N;
    const long long sCC  = (long long)S_LEN * S_LEN;

    // 0) zero rowsum; pack x; transpose+round+pack weights
    cudaMemsetAsync(rowsum, 0, BH_N * S_LEN * sizeof(float));
    pack_x_k<<<(M_ROWS * E_DIM / 32) / 256, 256>>>(x, xpk);
    transpose_pk_k<<<dim3(128, 32, 1), dim3(32, 8)>>>(W_up,   WupT,   1024, 4096, 0, 0);
    transpose_pk_k<<<dim3(32,  64, 1), dim3(32, 8)>>>(W_down, WdownT, 2048, 1024, 0, 0);

    // 1) up projection (wide tiles: 128x256, warp 64x64)
    gemm_wide<<<dim3(16, 32, 1), 256, SMEMW>>>(xpk, WupT, xinner, 1024, 4096, 0, 0, 0);
    // 2) causal conv + swish
    conv_swish_k<<<8192, 256>>>(xinner, conv_w, conv_b, xact);
    // 3) headwise q/k/v + gate preactivations (16 rows/block, weights L1-hot)
    qkv_gates_k<<<256, 256>>>(xinner, xact, Wq, Wk, Wv, W_ig, b_ig, W_fg, b_fg,
                              q, k, v, ig, fgp);
    // 3b) transpose+pack V per head (values already fp16-rounded)
    transpose_pk_h<<<dim3(16, 64, 8), dim3(32, 8)>>>(v, vT, 2048, 512, sQKV, sQKV);
    // 4) per-head scans
    scan_k<<<8, 256>>>(ig, fgp, a, amax, enm);
    // 5) weighted causal scores + fused row sums (C fp16 packed)
    gemm_qk<<<dim3(16, 16, 8), 256, SMEM>>>(q, k, Cb, 512, 2048,
                                            sQKV, sQKV, sCC, a, amax, rowsum,
                                            0.044194173824159216f);
    // 6+7) h = diag(1/norm) C @ V   (norm finalized inline)
    gemm_pv<<<dim3(2, 16, 8), 256, SMEMW>>>(Cb, vT, h, 2048, 512,
                                            sCC, sQKV, sQKV, rowsum, enm);
    // 8) multihead LN + skip + swish(z) gate (warp-per-row)
    ln_fuse_k<<<2048, 256>>>(h, xact, xinner, norm_w, skipw, hstate);
    // 9) down projection -> output (wide tiles)
    gemm_wide<<<dim3(4, 32, 1), 256, SMEMW>>>(hstate, WdownT, out, 2048, 1024, 0, 0, 0);
}

// round 17
// speedup vs baseline: 1.0871x; 1.0871x over previous
#include <cuda_runtime.h>
#include <cuda_fp16.h>
#include <math.h>
#include <stdint.h>

// Problem constants
#define S_LEN   2048
#define E_DIM   1024
#define INNER_D 2048
#define NH_N    4
#define DH_N    512
#define M_ROWS  4096   // B*S
#define BH_N    8      // B*NH
#define STAGES  3

// ---------------- scratch (device globals; no allocs allowed) ----------------
__device__ __half g_xpk   [(size_t)M_ROWS * E_DIM];      // packed fp16 x
__device__ float  g_xinner[(size_t)M_ROWS * 4096];
__device__ float  g_xact  [(size_t)M_ROWS * INNER_D];
__device__ __half g_q     [(size_t)BH_N * S_LEN * DH_N]; // packed fp16
__device__ __half g_k     [(size_t)BH_N * S_LEN * DH_N]; // packed fp16
__device__ __half g_v     [(size_t)BH_N * S_LEN * DH_N]; // fp16 (rounded at producer)
__device__ __half g_vT    [(size_t)BH_N * S_LEN * DH_N]; // packed fp16
__device__ __half g_C     [(size_t)BH_N * S_LEN * S_LEN];// packed fp16 (upper tri stays 0)
__device__ float  g_h     [(size_t)BH_N * S_LEN * DH_N]; // plain
__device__ __half g_hstate[(size_t)M_ROWS * INNER_D];    // packed fp16
__device__ __half g_WupT  [(size_t)4096 * 1024];         // packed fp16
__device__ __half g_WdownT[(size_t)1024 * 2048];         // packed fp16
__device__ float  g_ig    [BH_N * S_LEN];
__device__ float  g_fgp   [BH_N * S_LEN];
__device__ float  g_a     [BH_N * S_LEN];
__device__ float  g_amax  [BH_N * S_LEN];
__device__ float  g_enm   [BH_N * S_LEN];
__device__ float  g_rowsum[BH_N * S_LEN];

// ---------------- helpers ----------------
// packed half index within a row for element k (32-k groups, pair-interleaved,
// per-row group rotation): granule g holds pairs (p_g, p_{g+4}) of both 16-k chunks.
__device__ __forceinline__ int ppk(int r, int k) {
    int c = (k >> 4) & 1, kk = k & 15, p = kk >> 1;
    int g = ((p & 3) + ((r >> 1) & 3)) & 3;
    return (k & ~31) + g * 8 + (p >> 2) * 4 + c * 2 + (kk & 1);
}

__device__ __forceinline__ void mma16(float* d, uint32_t a0, uint32_t a1,
                                      uint32_t a2, uint32_t a3,
                                      uint32_t b0, uint32_t b1) {
    asm volatile(
        "mma.sync.aligned.m16n8k16.row.col.f32.f16.f16.f32 "
        "{%0,%1,%2,%3},{%4,%5,%6,%7},{%8,%9},{%0,%1,%2,%3};"
        : "+f"(d[0]), "+f"(d[1]), "+f"(d[2]), "+f"(d[3])
        : "r"(a0), "r"(a1), "r"(a2), "r"(a3), "r"(b0), "r"(b1));
}
__device__ __forceinline__ void cp16(uint32_t dst, const void* src) {
    asm volatile("cp.async.cg.shared.global [%0], [%1], 16;" :: "r"(dst), "l"(src));
}
__device__ __forceinline__ void cp_commit() {
    asm volatile("cp.async.commit_group;" ::: "memory");
}
template<int N>
__device__ __forceinline__ void cp_wait() {
    asm volatile("cp.async.wait_group %0;" :: "n"(N) : "memory");
}

// ---------------- fp16 tensor-core GEMM: C[M,N] = A[M,K] @ B[N,K]^T ---------
// Block tile 128x128x32, 8 warps (2x4 warp grid, warp tile 64x32), 2 blocks/SM.
// MODE 0: plain (float out)
// MODE 1: causal decay + fused row-sum; blocks n0 > m0+127 skipped;
//         strictly-lower tiles use rank-1 exp factorization;
//         C fp16 packed via smem-staged coalesced stores; quad-reduced atomics
template<int MODE>
__global__ __launch_bounds__(256, 2)
void gemm_tc(const __half* __restrict__ A, const __half* __restrict__ Bm,
             void* __restrict__ Cv, int Kd, int N,
             long long sA, long long sB, long long sC,
             const float* __restrict__ p1, const float* __restrict__ p2,
             float* __restrict__ rsum, float scale)
{
    const int my = (MODE != 0) ? (gridDim.y - 1 - blockIdx.y) : blockIdx.y;
    const int m0 = my * 128, n0 = blockIdx.x * 128;
    if (MODE == 1 && n0 > m0 + 127) return;   // never read by PV

    extern __shared__ char smemc[];   // A: [STAGES][128*64B], B: [STAGES][128*64B]
    const int bz = blockIdx.z;
    A  += (size_t)bz * sA;
    Bm += (size_t)bz * sB;
    const int tid = threadIdx.x, lane = tid & 31, warp = tid >> 5;
    const int wm = warp & 1, wn = warp >> 1;
    const int mbase = wm * 64, nbase = wn * 32;
    const int lr = lane >> 2, t4 = lane & 3;
    const int zb = bz * S_LEN;
    const int T = Kd >> 5;

    float acc[4][4][4];
#pragma unroll
    for (int i = 0; i < 4; i++)
#pragma unroll
        for (int j = 0; j < 4; j++)
#pragma unroll
            for (int r = 0; r < 4; r++) acc[i][j][r] = 0.f;

    const int arow = tid >> 1, agr = tid & 1;
    const __half* gA0 = A  + (size_t)(m0 + arow) * Kd + agr * 16;
    const __half* gB0 = Bm + (size_t)(n0 + arow) * Kd + agr * 16;
    const uint32_t sbase = (uint32_t)__cvta_generic_to_shared(smemc);
    const uint32_t dA = sbase + arow * 64 + agr * 32;
    const uint32_t dB = sbase + STAGES * 8192 + arow * 64 + agr * 32;

#pragma unroll
    for (int p = 0; p < 2; p++) {
        cp16(dA + p * 8192,      gA0 + p * 32);
        cp16(dA + p * 8192 + 16, gA0 + p * 32 + 8);
        cp16(dB + p * 8192,      gB0 + p * 32);
        cp16(dB + p * 8192 + 16, gB0 + p * 32 + 8);
        cp_commit();
    }

    for (int t = 0; t < T; t++) {
        if (t + 1 < T) cp_wait<1>(); else cp_wait<0>();
        __syncthreads();
        if (t + 2 < T) {
            const int stg = (t + 2) % STAGES;
            cp16(dA + stg * 8192,      gA0 + (t + 2) * 32);
            cp16(dA + stg * 8192 + 16, gA0 + (t + 2) * 32 + 8);
            cp16(dB + stg * 8192,      gB0 + (t + 2) * 32);
            cp16(dB + stg * 8192 + 16, gB0 + (t + 2) * 32 + 8);
            cp_commit();
        }
        const int stg = t % STAGES;
        const char* baseA = smemc + stg * 8192;
        const char* baseB = smemc + STAGES * 8192 + stg * 8192;
        uint4 af0[4], af1[4], bf[4];
#pragma unroll
        for (int mt = 0; mt < 4; mt++) {
            int r = mbase + mt * 16 + lr;
            int go = 16 * ((t4 + ((r >> 1) & 3)) & 3);
            af0[mt] = *(const uint4*)(baseA + r * 64 + go);
            af1[mt] = *(const uint4*)(baseA + (r + 8) * 64 + go);
        }
#pragma unroll
        for (int nt = 0; nt < 4; nt++) {
            int rb = nbase + nt * 8 + lr;
            int go = 16 * ((t4 + ((rb >> 1) & 3)) & 3);
            bf[nt] = *(const uint4*)(baseB + rb * 64 + go);
        }
#pragma unroll
        for (int mt = 0; mt < 4; mt++)
#pragma unroll
            for (int nt = 0; nt < 4; nt++) {
                mma16(acc[mt][nt], af0[mt].x, af1[mt].x, af0[mt].z, af1[mt].z,
                      bf[nt].x, bf[nt].z);
                mma16(acc[mt][nt], af0[mt].y, af1[mt].y, af0[mt].w, af1[mt].w,
                      bf[nt].y, bf[nt].w);
            }
    }

    if (MODE == 1) {
        __half* Ch = (__half*)Cv + (size_t)bz * sC;
        __syncthreads();
        __half* stg = (__half*)smemc;    // [128 rows][136 halves]
        float ac0[4], ac1[4];
#pragma unroll
        for (int nt = 0; nt < 4; nt++) {
            int c = n0 + nbase + nt * 8 + t4 * 2;
            ac0[nt] = p1[zb + c];
            ac1[nt] = p1[zb + c + 1];
        }
        const bool strict = (n0 + 128 <= m0);   // fully below diagonal
        float cf0[4], cf1[4], P = -3.4e38f;
        if (strict) {
#pragma unroll
            for (int nt = 0; nt < 4; nt++)
                P = fmaxf(P, fmaxf(ac0[nt], ac1[nt]));
            P = fmaxf(P, __shfl_xor_sync(0xffffffffu, P, 1));
            P = fmaxf(P, __shfl_xor_sync(0xffffffffu, P, 2));
#pragma unroll
            for (int nt = 0; nt < 4; nt++) {
                cf0[nt] = __expf(ac0[nt] - P);
                cf1[nt] = __expf(ac1[nt] - P);
            }
        }
#pragma unroll
        for (int mt = 0; mt < 4; mt++) {
            int r1 = m0 + mbase + mt * 16 + lr;
            int r2 = r1 + 8;
            float am1 = p2[zb + r1], am2 = p2[zb + r2];
            float rowacc1 = 0.f, rowacc2 = 0.f;
            float rf1 = 0.f, rf2 = 0.f;
            if (strict) {
                rf1 = scale * __expf(P - am1);
                rf2 = scale * __expf(P - am2);
            }
#pragma unroll
            for (int nt = 0; nt < 4; nt++) {
                int c = n0 + nbase + nt * 8 + t4 * 2;
                int cl = c - n0;
                float* a4 = acc[mt][nt];
                float o0, o1, o2, o3;
                if (strict) {
                    o0 = a4[0] * cf0[nt] * rf1;
                    o1 = a4[1] * cf1[nt] * rf1;
                    o2 = a4[2] * cf0[nt] * rf2;
                    o3 = a4[3] * cf1[nt] * rf2;
                } else {
                    o0 = a4[0] * ((c     <= r1) ? scale * __expf(fminf(ac0[nt] - am1, 0.f)) : 0.f);
                    o1 = a4[1] * ((c + 1 <= r1) ? scale * __expf(fminf(ac1[nt] - am1, 0.f)) : 0.f);
                    o2 = a4[2] * ((c     <= r2) ? scale * __expf(fminf(ac0[nt] - am2, 0.f)) : 0.f);
                    o3 = a4[3] * ((c + 1 <= r2) ? scale * __expf(fminf(ac1[nt] - am2, 0.f)) : 0.f);
                }
                rowacc1 += o0 + o1;
                rowacc2 += o2 + o3;
                *(__half2*)(stg + (r1 - m0) * 136 + ppk(r1, cl)) = __floats2half2_rn(o0, o1);
                *(__half2*)(stg + (r2 - m0) * 136 + ppk(r2, cl)) = __floats2half2_rn(o2, o3);
            }
            rowacc1 += __shfl_xor_sync(0xffffffffu, rowacc1, 1);
            rowacc1 += __shfl_xor_sync(0xffffffffu, rowacc1, 2);
            rowacc2 += __shfl_xor_sync(0xffffffffu, rowacc2, 1);
            rowacc2 += __shfl_xor_sync(0xffffffffu, rowacc2, 2);
            if (t4 == 0) {
                atomicAdd(rsum + zb + r1, rowacc1);
                atomicAdd(rsum + zb + r2, rowacc2);
            }
        }
        __syncthreads();
#pragma unroll
        for (int i = 0; i < 8; i++) {
            int idx = i * 256 + tid;
            int row = idx >> 4, col = idx & 15;
            uint4 vsm = *(const uint4*)(stg + row * 136 + col * 8);
            *(uint4*)(Ch + (size_t)(m0 + row) * N + n0 + col * 8) = vsm;
        }
        return;
    }

    // MODE 0 epilogue (float out)
    float* Cf = (float*)Cv + (size_t)bz * sC;
#pragma unroll
    for (int mt = 0; mt < 4; mt++) {
        int r1 = m0 + mbase + mt * 16 + lr;
        int r2 = r1 + 8;
#pragma unroll
        for (int nt = 0; nt < 4; nt++) {
            int c = n0 + nbase + nt * 8 + t4 * 2;
            float* a4 = acc[mt][nt];
            *(float2*)(Cf + (size_t)r1 * N + c) = make_float2(a4[0], a4[1]);
            *(float2*)(Cf + (size_t)r2 * N + c) = make_float2(a4[2], a4[3]);
        }
    }
}

// ---------------- PV GEMM: h[M,512] = diag(inorm) C[M,K] @ vT[512,K]^T ------
// Block tile 128x256x32, 8 warps (2x4 grid, warp tile 64x64), K trunc m0+128.
// inorm computed inline from rowsum/enm (finalize kernel folded in).
__global__ __launch_bounds__(256, 1)
void gemm_pv(const __half* __restrict__ A, const __half* __restrict__ Bm,
             float* __restrict__ Cf, int Kd, int N,
             long long sA, long long sB, long long sC,
             const float* __restrict__ rsum, const float* __restrict__ enm)
{
    const int my = gridDim.y - 1 - blockIdx.y;
    const int m0 = my * 128, n0 = blockIdx.x * 256;

    extern __shared__ char smemc[];   // A: [STAGES][128*64B]=24KB, B: [STAGES][256*64B]=48KB
    const int bz = blockIdx.z;
    A  += (size_t)bz * sA;
    Bm += (size_t)bz * sB;
    Cf += (size_t)bz * sC;
    const int tid = threadIdx.x, lane = tid & 31, warp = tid >> 5;
    const int wm = warp & 1, wn = warp >> 1;
    const int mbase = wm * 64, nbase = wn * 64;
    const int lr = lane >> 2, t4 = lane & 3;
    const int zb = bz * S_LEN;
    const int T = (m0 + 128) >> 5;

    float acc[4][8][4];
#pragma unroll
    for (int i = 0; i < 4; i++)
#pragma unroll
        for (int j = 0; j < 8; j++)
#pragma unroll
            for (int r = 0; r < 4; r++) acc[i][j][r] = 0.f;

    const int arow = tid >> 1, agr = tid & 1;
    const __half* gA0 = A  + (size_t)(m0 + arow) * Kd + agr * 16;
    const __half* gB0 = Bm + (size_t)(n0 + tid) * Kd;
    const uint32_t sbase = (uint32_t)__cvta_generic_to_shared(smemc);
    const uint32_t dA = sbase + arow * 64 + agr * 32;
    const uint32_t dB = sbase + STAGES * 8192 + tid * 64;

#pragma unroll
    for (int p = 0; p < 2; p++) {
        cp16(dA + p * 8192,      gA0 + p * 32);
        cp16(dA + p * 8192 + 16, gA0 + p * 32 + 8);
#pragma unroll
        for (int j = 0; j < 4; j++)
            cp16(dB + p * 16384 + j * 16, gB0 + p * 32 + j * 8);
        cp_commit();
    }

    for (int t = 0; t < T; t++) {
        if (t + 1 < T) cp_wait<1>(); else cp_wait<0>();
        __syncthreads();
        if (t + 2 < T) {
            const int stg = (t + 2) % STAGES;
            cp16(dA + stg * 8192,      gA0 + (t + 2) * 32);
            cp16(dA + stg * 8192 + 16, gA0 + (t + 2) * 32 + 8);
#pragma unroll
            for (int j = 0; j < 4; j++)
                cp16(dB + stg * 16384 + j * 16, gB0 + (t + 2) * 32 + j * 8);
            cp_commit();
        }
        const int stg = t % STAGES;
        const char* baseA = smemc + stg * 8192;
        const char* baseB = smemc + STAGES * 8192 + stg * 16384;
        uint4 af0[4], af1[4];
#pragma unroll
        for (int mt = 0; mt < 4; mt++) {
            int r = mbase + mt * 16 + lr;
            int go = 16 * ((t4 + ((r >> 1) & 3)) & 3);
            af0[mt] = *(const uint4*)(baseA + r * 64 + go);
            af1[mt] = *(const uint4*)(baseA + (r + 8) * 64 + go);
        }
#pragma unroll
        for (int half = 0; half < 2; half++) {
            uint4 bf[4];
#pragma unroll
            for (int j = 0; j < 4; j++) {
                int rb = nbase + (half * 4 + j) * 8 + lr;
                int go = 16 * ((t4 + ((rb >> 1) & 3)) & 3);
                bf[j] = *(const uint4*)(baseB + rb * 64 + go);
            }
#pragma unroll
            for (int mt = 0; mt < 4; mt++)
#pragma unroll
                for (int j = 0; j < 4; j++) {
                    float* a4 = acc[mt][half * 4 + j];
                    mma16(a4, af0[mt].x, af1[mt].x, af0[mt].z, af1[mt].z,
                          bf[j].x, bf[j].z);
                    mma16(a4, af0[mt].y, af1[mt].y, af0[mt].w, af1[mt].w,
                          bf[j].y, bf[j].w);
                }
        }
    }

#pragma unroll
    for (int mt = 0; mt < 4; mt++) {
        int r1 = m0 + mbase + mt * 16 + lr;
        int r2 = r1 + 8;
        float n1 = fmaxf(fabsf(rsum[zb + r1]), enm[zb + r1]);
        float n2 = fmaxf(fabsf(rsum[zb + r2]), enm[zb + r2]);
        float s1 = 1.f / (n1 + 1e-6f);
        float s2 = 1.f / (n2 + 1e-6f);
#pragma unroll
        for (int nt = 0; nt < 8; nt++) {
            int c = n0 + nbase + nt * 8 + t4 * 2;
            float* a4 = acc[mt][nt];
            *(float2*)(Cf + (size_t)r1 * N + c) = make_float2(a4[0] * s1, a4[1] * s1);
            *(float2*)(Cf + (size_t)r2 * N + c) = make_float2(a4[2] * s2, a4[3] * s2);
        }
    }
}

// ---------------- pack x to fp16 packed (one thread per 32-k group) ---------
__global__ void pack_x_k(const float* __restrict__ in, __half* __restrict__ out)
{
    int g = blockIdx.x * 256 + threadIdx.x;
    int r = g >> 5;
    const float* p = in + (size_t)g * 32;
    float buf[32];
#pragma unroll
    for (int i = 0; i < 8; i++) *(float4*)(buf + 4 * i) = *(const float4*)(p + 4 * i);
    __half hb[32];
#pragma unroll
    for (int j = 0; j < 32; j++) hb[ppk(r, j)] = __float2half_rn(buf[j]);
    uint4* o = (uint4*)(out + (size_t)g * 32);
#pragma unroll
    for (int i = 0; i < 4; i++) o[i] = ((uint4*)hb)[i];
}

// ---------------- transpose + fp16 round + pack (float in) ----------------
__global__ void transpose_pk_k(const float* __restrict__ in, __half* __restrict__ out,
                               int R, int Cc, long long sIn, long long sOut)
{
    __shared__ float tile[32][33];
    in  += (size_t)blockIdx.z * sIn;
    out += (size_t)blockIdx.z * sOut;
    int c0 = blockIdx.x * 32, r0 = blockIdx.y * 32;
    int x = threadIdx.x, y = threadIdx.y;
#pragma unroll
    for (int j = 0; j < 32; j += 8)
        tile[y + j][x] = in[(size_t)(r0 + y + j) * Cc + c0 + x];
    __syncthreads();
#pragma unroll
    for (int j = 0; j < 32; j += 8) {
        int orow = c0 + y + j;
        out[(size_t)orow * R + r0 + ppk(orow, x)] = __float2half_rn(tile[x][y + j]);
    }
}

// ---------------- transpose + pack (half in; values already rounded) --------
__global__ void transpose_pk_h(const __half* __restrict__ in, __half* __restrict__ out,
                               int R, int Cc, long long sIn, long long sOut)
{
    __shared__ __half tile[32][34];
    in  += (size_t)blockIdx.z * sIn;
    out += (size_t)blockIdx.z * sOut;
    int c0 = blockIdx.x * 32, r0 = blockIdx.y * 32;
    int x = threadIdx.x, y = threadIdx.y;
#pragma unroll
    for (int j = 0; j < 32; j += 8)
        tile[y + j][x] = in[(size_t)(r0 + y + j) * Cc + c0 + x];
    __syncthreads();
#pragma unroll
    for (int j = 0; j < 32; j += 8) {
        int orow = c0 + y + j;
        out[(size_t)orow * R + r0 + ppk(orow, x)] = tile[x][y + j];
    }
}

// ---------------- causal depthwise conv (K=4) + swish, 4 elems/thread -------
__global__ void conv_swish_k(const float* __restrict__ xinner,
                             const float* __restrict__ cw,
                             const float* __restrict__ cb,
                             float* __restrict__ xact)
{
    int idx = blockIdx.x * 256 + threadIdx.x;
    int c = (idx << 2) & 2047;
    int r = idx >> 9;
    int s = r & 2047;
    const float* base = xinner + (size_t)r * 4096 + c;
    float4 acc = *(const float4*)(cb + c);
#pragma unroll
    for (int i = 0; i < 4; i++) {
        int sp = s - 3 + i;
        if (sp >= 0) {
            float4 xv = *(const float4*)(base + (long long)(i - 3) * 4096);
            float4 w  = *(const float4*)(cw + i * 2048 + c);
            acc.x = fmaf(xv.x, w.x, acc.x);
            acc.y = fmaf(xv.y, w.y, acc.y);
            acc.z = fmaf(xv.z, w.z, acc.z);
            acc.w = fmaf(xv.w, w.w, acc.w);
        }
    }
    float4 o;
    o.x = acc.x / (1.f + __expf(-acc.x));
    o.y = acc.y / (1.f + __expf(-acc.y));
    o.z = acc.z / (1.f + __expf(-acc.z));
    o.w = acc.w / (1.f + __expf(-acc.w));
    *(float4*)(xact + (size_t)idx * 4) = o;
}

// ---------------- headwise q/k/v + gates: 16 rows/block, weights L1-reused --
__global__ __launch_bounds__(256)
void qkv_gates_k(const float* __restrict__ xinner, const float* __restrict__ xact,
    const float* __restrict__ Wq, const float* __restrict__ Wk, const float* __restrict__ Wv,
    const float* __restrict__ Wig, const float* __restrict__ big,
    const float* __restrict__ Wfg, const float* __restrict__ bfg,
    __half* __restrict__ q, __half* __restrict__ k, __half* __restrict__ v,
    float* __restrict__ ig, float* __restrict__ fgp)
{
    const int tid = threadIdx.x;
    __shared__ float red[8][8];
    const int wid = tid >> 5, lane = tid & 31;

    for (int rr = 0; rr < 16; rr++) {
        const int r = blockIdx.x * 16 + rr;
        const int b = r >> 11, s = r & 2047;
        float igp[4] = {0, 0, 0, 0}, fgv[4] = {0, 0, 0, 0};
#pragma unroll
        for (int g = 0; g < 2; g++) {
            int c4 = tid * 8 + g * 4;
            int ph = c4 >> 2;
            float4 xa = *(const float4*)(xact + (size_t)r * 2048 + c4);
            float4 xm = *(const float4*)(xinner + (size_t)r * 4096 + c4);
            float qv[4], kv[4], vv[4];
            int nh = c4 >> 9, dh0 = c4 & 511;
            size_t rowb = ((size_t)(b * 4 + nh) * 2048 + s) * 512;
            const float4* Wq4 = (const float4*)(Wq + ph * 16);
            const float4* Wk4 = (const float4*)(Wk + ph * 16);
            const float4* Wv4 = (const float4*)(Wv + ph * 16);
#pragma unroll
            for (int o = 0; o < 4; o++) {
                float4 wq = Wq4[o], wk = Wk4[o], wv = Wv4[o];
                float qo = 0.f, ko = 0.f, vo = 0.f;
                qo = fmaf(xa.x, wq.x, qo); qo = fmaf(xa.y, wq.y, qo);
                qo = fmaf(xa.z, wq.z, qo); qo = fmaf(xa.w, wq.w, qo);
                ko = fmaf(xa.x, wk.x, ko); ko = fmaf(xa.y, wk.y, ko);
                ko = fmaf(xa.z, wk.z, ko); ko = fmaf(xa.w, wk.w, ko);
                vo = fmaf(xm.x, wv.x, vo); vo = fmaf(xm.y, wv.y, vo);
                vo = fmaf(xm.z, wv.z, vo); vo = fmaf(xm.w, wv.w, vo);
                qv[o] = qo; kv[o] = ko; vv[o] = vo;
                int c = c4 + o;
                float4 wiq = *(const float4*)(Wig + c * 4);
                float4 wik = *(const float4*)(Wig + (2048 + c) * 4);
                float4 wiv = *(const float4*)(Wig + (4096 + c) * 4);
                float4 wfq = *(const float4*)(Wfg + c * 4);
                float4 wfk = *(const float4*)(Wfg + (2048 + c) * 4);
                float4 wfv = *(const float4*)(Wfg + (4096 + c) * 4);
                const float* aiq = (const float*)&wiq;
                const float* aik = (const float*)&wik;
                const float* aiv = (const float*)&wiv;
                const float* afq = (const float*)&wfq;
                const float* afk = (const float*)&wfk;
                const float* afv = (const float*)&wfv;
#pragma unroll
                for (int n2 = 0; n2 < 4; n2++) {
                    igp[n2] = fmaf(qo, aiq[n2], igp[n2]);
                    igp[n2] = fmaf(ko, aik[n2], igp[n2]);
                    igp[n2] = fmaf(vo, aiv[n2], igp[n2]);
                    fgv[n2] = fmaf(qo, afq[n2], fgv[n2]);
                    fgv[n2] = fmaf(ko, afk[n2], fgv[n2]);
                    fgv[n2] = fmaf(vo, afv[n2], fgv[n2]);
                }
            }
            *(__half2*)(q + rowb + ppk(s, dh0))     = __floats2half2_rn(qv[0], qv[1]);
            *(__half2*)(q + rowb + ppk(s, dh0 + 2)) = __floats2half2_rn(qv[2], qv[3]);
            *(__half2*)(k + rowb + ppk(s, dh0))     = __floats2half2_rn(kv[0], kv[1]);
            *(__half2*)(k + rowb + ppk(s, dh0 + 2)) = __floats2half2_rn(kv[2], kv[3]);
            *(__half2*)(v + rowb + dh0)             = __floats2half2_rn(vv[0], vv[1]);
            *(__half2*)(v + rowb + dh0 + 2)         = __floats2half2_rn(vv[2], vv[3]);
        }
#pragma unroll
        for (int off = 16; off; off >>= 1) {
#pragma unroll
            for (int n2 = 0; n2 < 4; n2++) {
                igp[n2] += __shfl_down_sync(0xffffffffu, igp[n2], off);
                fgv[n2] += __shfl_down_sync(0xffffffffu, fgv[n2], off);
            }
        }
        if (lane == 0) {
#pragma unroll
            for (int n2 = 0; n2 < 4; n2++) { red[wid][n2] = igp[n2]; red[wid][4 + n2] = fgv[n2]; }
        }
        __syncthreads();
        if (tid < 8) {
            float acc = 0.f;
            for (int w = 0; w < 8; w++) acc += red[w][tid];
            int n2 = tid & 3;
            if (tid < 4) ig [(size_t)(b * 4 + n2) * 2048 + s] = acc + big[n2];
            else         fgp[(size_t)(b * 4 + n2) * 2048 + s] = acc + bfg[n2];
        }
        __syncthreads();
    }
}

// ---------------- per-head scans ----------------
__global__ void scan_k(const float* __restrict__ ig, const float* __restrict__ fgp,
                       float* __restrict__ ga, float* __restrict__ gamax,
                       float* __restrict__ genm)
{
    const int bh = blockIdx.x, tid = threadIdx.x;
    const int base = bh * 2048;
    const int lane = tid & 31, warp = tid >> 5;
    float lf[8], aL[8], F[8];
    float s = 0.f;
#pragma unroll
    for (int j = 0; j < 8; j++) {
        float xv = fgp[base + tid * 8 + j];
        lf[j] = fminf(xv, 0.f) - log1pf(expf(-fabsf(xv)));
        s += lf[j];
    }
    __shared__ float wred[8];
    float inc = s;
#pragma unroll
    for (int off = 1; off < 32; off <<= 1) {
        float o = __shfl_up_sync(0xffffffffu, inc, off);
        if (lane >= off) inc += o;
    }
    float exc = __shfl_up_sync(0xffffffffu, inc, 1);
    if (lane == 0) exc = 0.f;
    if (lane == 31) wred[warp] = inc;
    __syncthreads();
    float wofs = 0.f;
#pragma unroll
    for (int w = 0; w < 8; w++) if (w < warp) wofs += wred[w];
    float run = wofs + exc;
#pragma unroll
    for (int j = 0; j < 8; j++) { run += lf[j]; F[j] = run; }
    __syncthreads();

    float mloc = -3.4e38f;
#pragma unroll
    for (int j = 0; j < 8; j++) {
        aL[j] = ig[base + tid * 8 + j] - F[j];
        mloc = fmaxf(mloc, aL[j]);
    }
    float minc = mloc;
#pragma unroll
    for (int off = 1; off < 32; off <<= 1) {
        float o = __shfl_up_sync(0xffffffffu, minc, off);
        if (lane >= off) minc = fmaxf(minc, o);
    }
    float mexc = __shfl_up_sync(0xffffffffu, minc, 1);
    if (lane == 0) mexc = -3.4e38f;
    if (lane == 31) wred[warp] = minc;
    __syncthreads();
    float wm = -3.4e38f;
#pragma unroll
    for (int w = 0; w < 8; w++) if (w < warp) wm = fmaxf(wm, wred[w]);
    float rm = fmaxf(wm, mexc);
#pragma unroll
    for (int j = 0; j < 8; j++) {
        rm = fmaxf(rm, aL[j]);
        int idx = base + tid * 8 + j;
        ga[idx] = aL[j];
        gamax[idx] = rm;
        genm[idx] = expf(-(F[j] + rm));
    }
}

// ---------------- layernorm + skip + swish(z): warp-per-(row,head) ----------
__global__ __launch_bounds__(256)
void ln_fuse_k(const float* __restrict__ h, const float* __restrict__ xact,
    const float* __restrict__ xinner, const float* __restrict__ nw,
    const float* __restrict__ sk, __half* __restrict__ hstate)
{
    const int warp = threadIdx.x >> 5, lane = threadIdx.x & 31;
    const int idx = blockIdx.x * 8 + warp;     // [0, 16384)
    const int r = idx >> 2, nh = idx & 3;
    const int b = r >> 11, s = r & 2047;
    const float* hp = h + ((size_t)(b * 4 + nh) * 2048 + s) * 512;

    float4 hv[4];
    float sum = 0.f;
#pragma unroll
    for (int j = 0; j < 4; j++) {
        hv[j] = *(const float4*)(hp + j * 128 + lane * 4);
        sum += hv[j].x + hv[j].y + hv[j].z + hv[j].w;
    }
#pragma unroll
    for (int off = 16; off; off >>= 1) sum += __shfl_xor_sync(0xffffffffu, sum, off);
    const float mu = sum * (1.f / 512.f);

    float sq = 0.f;
#pragma unroll
    for (int j = 0; j < 4; j++) {
        float dx = hv[j].x - mu, dy = hv[j].y - mu, dz = hv[j].z - mu, dw = hv[j].w - mu;
        sq += dx * dx + dy * dy + dz * dz + dw * dw;
    }
#pragma unroll
    for (int off = 16; off; off >>= 1) sq += __shfl_xor_sync(0xffffffffu, sq, off);
    const float rstd = rsqrtf(sq * (1.f / 512.f) + 1e-6f);

    __half* hb = hstate + (size_t)r * 2048;
#pragma unroll
    for (int j = 0; j < 4; j++) {
        int c0 = nh * 512 + j * 128 + lane * 4;
        float4 nwv = *(const float4*)(nw + c0);
        float4 skv = *(const float4*)(sk + c0);
        float4 xav = *(const float4*)(xact + (size_t)r * 2048 + c0);
        float4 zv  = *(const float4*)(xinner + (size_t)r * 4096 + 2048 + c0);
        float o0 = ((hv[j].x - mu) * rstd * nwv.x + skv.x * xav.x) * (zv.x / (1.f + __expf(-zv.x)));
        float o1 = ((hv[j].y - mu) * rstd * nwv.y + skv.y * xav.y) * (zv.y / (1.f + __expf(-zv.y)));
        float o2 = ((hv[j].z - mu) * rstd * nwv.z + skv.z * xav.z) * (zv.z / (1.f + __expf(-zv.z)));
        float o3 = ((hv[j].w - mu) * rstd * nwv.w + skv.w * xav.w) * (zv.w / (1.f + __expf(-zv.w)));
        *(__half2*)(hb + ppk(r, c0))     = __floats2half2_rn(o0, o1);
        *(__half2*)(hb + ppk(r, c0 + 2)) = __floats2half2_rn(o2, o3);
    }
}

// ---------------- launch ----------------
extern "C" void kernel_launch(void* const* d_in, const int* in_sizes, int n_in,
                              void* d_out, int out_size)
{
    (void)in_sizes; (void)n_in; (void)out_size;
    const float* x      = (const float*)d_in[0];
    const float* W_up   = (const float*)d_in[1];
    const float* conv_w = (const float*)d_in[2];
    const float* conv_b = (const float*)d_in[3];
    const float* Wq     = (const float*)d_in[4];
    const float* Wk     = (const float*)d_in[5];
    const float* Wv     = (const float*)d_in[6];
    const float* W_ig   = (const float*)d_in[7];
    const float* b_ig   = (const float*)d_in[8];
    const float* W_fg   = (const float*)d_in[9];
    const float* b_fg   = (const float*)d_in[10];
    const float* norm_w = (const float*)d_in[11];
    const float* skipw  = (const float*)d_in[12];
    const float* W_down = (const float*)d_in[13];
    float* out = (float*)d_out;

    __half *xpk, *q, *k, *v, *vT, *Cb, *hstate, *WupT, *WdownT;
    float *xinner, *xact, *h;
    float *ig, *fgp, *a, *amax, *enm, *rowsum;
    cudaGetSymbolAddress((void**)&xpk,    g_xpk);
    cudaGetSymbolAddress((void**)&xinner, g_xinner);
    cudaGetSymbolAddress((void**)&xact,   g_xact);
    cudaGetSymbolAddress((void**)&q,      g_q);
    cudaGetSymbolAddress((void**)&k,      g_k);
    cudaGetSymbolAddress((void**)&v,      g_v);
    cudaGetSymbolAddress((void**)&vT,     g_vT);
    cudaGetSymbolAddress((void**)&Cb,     g_C);
    cudaGetSymbolAddress((void**)&h,      g_h);
    cudaGetSymbolAddress((void**)&hstate, g_hstate);
    cudaGetSymbolAddress((void**)&WupT,   g_WupT);
    cudaGetSymbolAddress((void**)&WdownT, g_WdownT);
    cudaGetSymbolAddress((void**)&ig,     g_ig);
    cudaGetSymbolAddress((void**)&fgp,    g_fgp);
    cudaGetSymbolAddress((void**)&a,      g_a);
    cudaGetSymbolAddress((void**)&amax,   g_amax);
    cudaGetSymbolAddress((void**)&enm,    g_enm);
    cudaGetSymbolAddress((void**)&rowsum, g_rowsum);

    const int SMEM   = STAGES * (8192 + 8192);    // 48 KB
    const int SMEMPV = STAGES * (8192 + 16384);   // 72 KB
    cudaFuncSetAttribute((const void*)gemm_tc<0>, cudaFuncAttributeMaxDynamicSharedMemorySize, SMEM);
    cudaFuncSetAttribute((const void*)gemm_tc<1>, cudaFuncAttributeMaxDynamicSharedMemorySize, SMEM);
    cudaFuncSetAttribute((const void*)gemm_pv,    cudaFuncAttributeMaxDynamicSharedMemorySize, SMEMPV);

    const long long sQKV = (long long)S_LEN * DH_N;
    const long long sCC  = (long long)S_LEN * S_LEN;

    // 0) zero rowsum; pack x; transpose+round+pack weights
    cudaMemsetAsync(rowsum, 0, BH_N * S_LEN * sizeof(float));
    pack_x_k<<<(M_ROWS * E_DIM / 32) / 256, 256>>>(x, xpk);
    transpose_pk_k<<<dim3(128, 32, 1), dim3(32, 8)>>>(W_up,   WupT,   1024, 4096, 0, 0);
    transpose_pk_k<<<dim3(32,  64, 1), dim3(32, 8)>>>(W_down, WdownT, 2048, 1024, 0, 0);

    // 1) up projection
    gemm_tc<0><<<dim3(32, 32, 1), 256, SMEM>>>(xpk, WupT, xinner, 1024, 4096,
                                               0, 0, 0, nullptr, nullptr, nullptr, 0.f);
    // 2) causal conv + swish
    conv_swish_k<<<8192, 256>>>(xinner, conv_w, conv_b, xact);
    // 3) headwise q/k/v + gate preactivations (16 rows/block, weights L1-hot)
    qkv_gates_k<<<256, 256>>>(xinner, xact, Wq, Wk, Wv, W_ig, b_ig, W_fg, b_fg,
                              q, k, v, ig, fgp);
    // 3b) transpose+pack V per head (values already fp16-rounded)
    transpose_pk_h<<<dim3(16, 64, 8), dim3(32, 8)>>>(v, vT, 2048, 512, sQKV, sQKV);
    // 4) per-head scans
    scan_k<<<8, 256>>>(ig, fgp, a, amax, enm);
    // 5) weighted causal scores + fused row sums (C fp16 packed)
    gemm_tc<1><<<dim3(16, 16, 8), 256, SMEM>>>(q, k, Cb, 512, 2048,
                                               sQKV, sQKV, sCC, a, amax, rowsum,
                                               0.044194173824159216f);
    // 6+7) h = diag(1/norm) C @ V   (norm finalized inline from rowsum/enm)
    gemm_pv<<<dim3(2, 16, 8), 256, SMEMPV>>>(Cb, vT, h, 2048, 512,
                                             sCC, sQKV, sQKV, rowsum, enm);
    // 8) multihead LN + skip + swish(z) gate (warp-per-row)
    ln_fuse_k<<<2048, 256>>>(h, xact, xinner, norm_w, skipw, hstate);
    // 9) down projection -> output
    gemm_tc<0><<<dim3(8, 32, 1), 256, SMEM>>>(hstate, WdownT, out, 2048, 1024,
                                              0, 0, 0, nullptr, nullptr, nullptr, 0.f);
}